// round 5
// baseline (speedup 1.0000x reference)
#include <cuda_runtime.h>
#include <cuda_fp16.h>
#include <math.h>

#define BB 2
#define CC 256
#define HH 200
#define WW 304
#define HW (HH * WW)
#define OUTH 7
#define OUTW 7
#define NBINS (OUTH * OUTW)
#define SRR 2
#define NSAMP (OUTH * SRR * OUTW * SRR)   /* 196 */
#define SCALE 0.25f

// NHWC fp16 scratch as uint4 so 16-byte gathers are guaranteed aligned.
// (B, H, W, C) halves = BB*HW*(CC/8) uint4 = 62.3 MB (L2-resident).
__device__ uint4 g_nhwc4[(size_t)BB * HW * (CC / 8)];

// ---------------------------------------------------------------------------
// Kernel 1: NCHW f32 -> NHWC fp16. Tile 64 channels x 32 hw positions.
// ---------------------------------------------------------------------------
__global__ __launch_bounds__(256) void nchw_to_nhwc_h(const float* __restrict__ in) {
    __shared__ float tile[64][33];
    const int b   = blockIdx.z;
    const int hw0 = blockIdx.x * 32;
    const int c0  = blockIdx.y * 64;
    const int tx  = threadIdx.x;       // 0..31
    const int ty  = threadIdx.y;       // 0..7

    const float* src = in + (size_t)b * CC * HW;
#pragma unroll
    for (int i = 0; i < 64; i += 8) {
        int c  = c0 + ty + i;
        int hw = hw0 + tx;
        float v = 0.0f;
        if (hw < HW) v = src[(size_t)c * HW + hw];
        tile[ty + i][tx] = v;
    }
    __syncthreads();

    __half2* dst = (__half2*)g_nhwc4 + (size_t)b * HW * (CC / 2);
#pragma unroll
    for (int i = 0; i < 32; i += 8) {
        int hw = hw0 + ty + i;
        if (hw < HW) {
            float va = tile[2 * tx][ty + i];
            float vb = tile[2 * tx + 1][ty + i];
            dst[((size_t)hw * CC + c0) / 2 + tx] = __floats2half2_rn(va, vb);
        }
    }
}

// ---------------------------------------------------------------------------
// Kernel 2: rotated ROI align on fp16 NHWC.
// Grid (n_rois, 2), block 128 = 4 warps. Warp s = one bin subgroup:
// bins [28*y + 7s, +7). Each lane owns 8 channels (uint4 = 16B gathers,
// 512B/warp per corner). fp32 accumulation, per-warp fp16 stage region
// (no __syncthreads in the main loop), coalesced f32 flush per warp.
// ---------------------------------------------------------------------------
#define TPB 128

struct AlignSmem {
    int4   o[NSAMP];             // 4 corner offsets in uint4 units (pix*32)
    float4 w[NSAMP];             // 4 bilinear weights (zeroed if empty)
    __half stage[4][7][264];     // [warp][bin-in-range][channel(+pad)]
    int    base_b;
};

__global__ __launch_bounds__(TPB, 8) void roi_align_rotated(
    const float* __restrict__ rois, float* __restrict__ out) {
    __shared__ AlignSmem sm;
    const int n    = blockIdx.x;
    const int tid  = threadIdx.x;
    const int sub  = tid >> 5;        // warp id 0..3 = bin subgroup
    const int lane = tid & 31;        // 8 channels per lane
    const float* r = rois + (size_t)n * 6;

#pragma unroll
    for (int s = tid; s < NSAMP; s += TPB) {
        float cw = r[1] * SCALE - 0.5f;
        float ch = r[2] * SCALE - 0.5f;
        float rw = r[3] * SCALE;
        float rh = r[4] * SCALE;
        float theta = r[5] * (float)(M_PI / 180.0);
        float st, ct;
        sincosf(theta, &st, &ct);

        int i = s / (OUTW * SRR);   // y sample index 0..13
        int j = s % (OUTW * SRR);   // x sample index 0..13
        float bin_h = rh * (1.0f / OUTH);
        float bin_w = rw * (1.0f / OUTW);
        float ty = (i + 0.5f) * (1.0f / SRR);
        float tx = (j + 0.5f) * (1.0f / SRR);
        float yy = -rh * 0.5f + ty * bin_h;
        float xx = -rw * 0.5f + tx * bin_w;
        float y = yy * ct - xx * st + ch;
        float x = yy * st + xx * ct + cw;

        bool empty = (y < -1.0f) | (y > (float)HH) | (x < -1.0f) | (x > (float)WW);
        y = fmaxf(y, 0.0f);
        x = fmaxf(x, 0.0f);
        int yl = min((int)floorf(y), HH - 1);
        int xl = min((int)floorf(x), WW - 1);
        int yh = min(yl + 1, HH - 1);
        int xh = min(xl + 1, WW - 1);
        float ly = fminf(y - (float)yl, 1.0f);
        float lx = fminf(x - (float)xl, 1.0f);
        float hy = 1.0f - ly, hx = 1.0f - lx;
        float w1 = hy * hx, w2 = hy * lx, w3 = ly * hx, w4 = ly * lx;
        if (empty) { w1 = w2 = w3 = w4 = 0.0f; }

        // offsets in uint4 (=8 half) units: pixel * CC/8 = pixel * 32
        sm.o[s] = make_int4((yl * WW + xl) * (CC / 8), (yl * WW + xh) * (CC / 8),
                            (yh * WW + xl) * (CC / 8), (yh * WW + xh) * (CC / 8));
        sm.w[s] = make_float4(w1, w2, w3, w4);
    }
    if (tid == 0) sm.base_b = (int)r[0];
    __syncthreads();

    const int b0 = 28 * blockIdx.y + 7 * sub;     // 0,7,14,21 / 28,35,42,49
    if (b0 >= NBINS) return;                      // warp 3 of y=1 idles

    // lane owns channels {8*lane .. 8*lane+7}
    const uint4* __restrict__ f =
        g_nhwc4 + (size_t)sm.base_b * (HW * (CC / 8)) + lane;
    float* __restrict__ o_roi = out + (size_t)n * (CC * NBINS);

#pragma unroll 1
    for (int bi = 0; bi < 7; bi++) {
        int bin = b0 + bi;
        int ph = bin / OUTW, pw = bin % OUTW;
        float a0 = 0.f, a1 = 0.f, a2 = 0.f, a3 = 0.f;
        float a4 = 0.f, a5 = 0.f, a6 = 0.f, a7 = 0.f;
#pragma unroll
        for (int iy = 0; iy < SRR; iy++) {
#pragma unroll
            for (int ix = 0; ix < SRR; ix++) {
                int s = (ph * SRR + iy) * (OUTW * SRR) + (pw * SRR + ix);
                int4   o = sm.o[s];
                float4 w = sm.w[s];
                uint4 p1 = __ldg(f + o.x);
                uint4 p2 = __ldg(f + o.y);
                uint4 p3 = __ldg(f + o.z);
                uint4 p4 = __ldg(f + o.w);
                float2 v;
                v = __half22float2(*(__half2*)&p1.x); a0 += w.x * v.x; a1 += w.x * v.y;
                v = __half22float2(*(__half2*)&p1.y); a2 += w.x * v.x; a3 += w.x * v.y;
                v = __half22float2(*(__half2*)&p1.z); a4 += w.x * v.x; a5 += w.x * v.y;
                v = __half22float2(*(__half2*)&p1.w); a6 += w.x * v.x; a7 += w.x * v.y;
                v = __half22float2(*(__half2*)&p2.x); a0 += w.y * v.x; a1 += w.y * v.y;
                v = __half22float2(*(__half2*)&p2.y); a2 += w.y * v.x; a3 += w.y * v.y;
                v = __half22float2(*(__half2*)&p2.z); a4 += w.y * v.x; a5 += w.y * v.y;
                v = __half22float2(*(__half2*)&p2.w); a6 += w.y * v.x; a7 += w.y * v.y;
                v = __half22float2(*(__half2*)&p3.x); a0 += w.z * v.x; a1 += w.z * v.y;
                v = __half22float2(*(__half2*)&p3.y); a2 += w.z * v.x; a3 += w.z * v.y;
                v = __half22float2(*(__half2*)&p3.z); a4 += w.z * v.x; a5 += w.z * v.y;
                v = __half22float2(*(__half2*)&p3.w); a6 += w.z * v.x; a7 += w.z * v.y;
                v = __half22float2(*(__half2*)&p4.x); a0 += w.w * v.x; a1 += w.w * v.y;
                v = __half22float2(*(__half2*)&p4.y); a2 += w.w * v.x; a3 += w.w * v.y;
                v = __half22float2(*(__half2*)&p4.z); a4 += w.w * v.x; a5 += w.w * v.y;
                v = __half22float2(*(__half2*)&p4.w); a6 += w.w * v.x; a7 += w.w * v.y;
            }
        }
        // pack 8 results as 8 halves -> one 16B smem store per lane
        __half2 h01 = __floats2half2_rn(a0 * 0.25f, a1 * 0.25f);
        __half2 h23 = __floats2half2_rn(a2 * 0.25f, a3 * 0.25f);
        __half2 h45 = __floats2half2_rn(a4 * 0.25f, a5 * 0.25f);
        __half2 h67 = __floats2half2_rn(a6 * 0.25f, a7 * 0.25f);
        uint4 pk;
        pk.x = *(unsigned*)&h01;
        pk.y = *(unsigned*)&h23;
        pk.z = *(unsigned*)&h45;
        pk.w = *(unsigned*)&h67;
        *((uint4*)&sm.stage[sub][bi][0] + lane) = pk;
    }
    __syncwarp();

    // per-warp coalesced-ish flush: runs of 7 consecutive floats per channel
    for (int k = lane; k < CC * 7; k += 32) {
        int c  = k / 7;
        int bb = k - c * 7;
        o_roi[c * NBINS + b0 + bb] = __half2float(sm.stage[sub][bb][c]);
    }
}

// ---------------------------------------------------------------------------
extern "C" void kernel_launch(void* const* d_in, const int* in_sizes, int n_in,
                              void* d_out, int out_size) {
    const float* feats = (const float*)d_in[0];  // (2,256,200,304) f32
    const float* rois  = (const float*)d_in[1];  // (N,6) f32
    float* out = (float*)d_out;                  // (N,256,7,7) f32
    int n_rois = in_sizes[1] / 6;

    dim3 tgrid((HW + 31) / 32, CC / 64, BB);
    nchw_to_nhwc_h<<<tgrid, dim3(32, 8)>>>(feats);

    roi_align_rotated<<<dim3(n_rois, 2), TPB>>>(rois, out);
}

// round 6
// speedup vs baseline: 1.2863x; 1.2863x over previous
#include <cuda_runtime.h>
#include <cuda_fp16.h>
#include <math.h>

#define BB 2
#define CC 256
#define HH 200
#define WW 304
#define HW (HH * WW)
#define OUTH 7
#define OUTW 7
#define NBINS (OUTH * OUTW)
#define SRR 2
#define NSAMP (OUTH * SRR * OUTW * SRR)   /* 196 */
#define SCALE 0.25f

// NHWC fp16 scratch as uint2 so 8-byte gathers are guaranteed aligned.
// (B, H, W, C) halves = 62.3 MB (L2-resident).
__device__ uint2 g_nhwc2[(size_t)BB * HW * (CC / 4)];

// ---------------------------------------------------------------------------
// Kernel 1: NCHW f32 -> NHWC fp16. Tile 64 channels x 32 hw positions.
// ---------------------------------------------------------------------------
__global__ __launch_bounds__(256) void nchw_to_nhwc_h(const float* __restrict__ in) {
    __shared__ float tile[64][33];
    const int b   = blockIdx.z;
    const int hw0 = blockIdx.x * 32;
    const int c0  = blockIdx.y * 64;
    const int tx  = threadIdx.x;       // 0..31
    const int ty  = threadIdx.y;       // 0..7

    const float* src = in + (size_t)b * CC * HW;
#pragma unroll
    for (int i = 0; i < 64; i += 8) {
        int c  = c0 + ty + i;
        int hw = hw0 + tx;
        float v = 0.0f;
        if (hw < HW) v = src[(size_t)c * HW + hw];
        tile[ty + i][tx] = v;
    }
    __syncthreads();

    __half2* dst = (__half2*)g_nhwc2 + (size_t)b * HW * (CC / 2);
#pragma unroll
    for (int i = 0; i < 32; i += 8) {
        int hw = hw0 + ty + i;
        if (hw < HW) {
            float va = tile[2 * tx][ty + i];
            float vb = tile[2 * tx + 1][ty + i];
            dst[((size_t)hw * CC + c0) / 2 + tx] = __floats2half2_rn(va, vb);
        }
    }
}

// ---------------------------------------------------------------------------
// Kernel 2: rotated ROI align on fp16 NHWC.
// Grid (n_rois, 4), block 128 = 2 subgroups of 64 threads.
// Subgroup handles ONE 7-bin chunk: chunk = 2*blockIdx.y + sub (0..7; chunk 7
// idles). 4 ch/thread via uint2 (8B) gathers, fp32 accumulation, fp16 stage,
// coalesced f32 flush. 48-reg / 14KB operating point (R4's best).
// ---------------------------------------------------------------------------
#define TPB 128

struct AlignSmem {
    int4   o[NSAMP];             // 4 corner offsets in uint2 units (pix*64)
    float4 w[NSAMP];             // 4 bilinear weights (zeroed if empty)
    __half stage[2][7][264];     // [subgroup][bin-in-chunk][channel(+pad)]
    int    base_b;
};

__global__ __launch_bounds__(TPB, 10) void roi_align_rotated(
    const float* __restrict__ rois, float* __restrict__ out) {
    __shared__ AlignSmem sm;
    const int n   = blockIdx.x;
    const int tid = threadIdx.x;
    const int sub = tid >> 6;        // 0/1: chunk subgroup
    const int lt  = tid & 63;        // channel-group lane
    const float* r = rois + (size_t)n * 6;

#pragma unroll
    for (int s = tid; s < NSAMP; s += TPB) {
        float cw = r[1] * SCALE - 0.5f;
        float ch = r[2] * SCALE - 0.5f;
        float rw = r[3] * SCALE;
        float rh = r[4] * SCALE;
        float theta = r[5] * (float)(M_PI / 180.0);
        float st, ct;
        sincosf(theta, &st, &ct);

        int i = s / (OUTW * SRR);   // y sample index 0..13
        int j = s % (OUTW * SRR);   // x sample index 0..13
        float bin_h = rh * (1.0f / OUTH);
        float bin_w = rw * (1.0f / OUTW);
        float ty = (i + 0.5f) * (1.0f / SRR);
        float tx = (j + 0.5f) * (1.0f / SRR);
        float yy = -rh * 0.5f + ty * bin_h;
        float xx = -rw * 0.5f + tx * bin_w;
        float y = yy * ct - xx * st + ch;
        float x = yy * st + xx * ct + cw;

        bool empty = (y < -1.0f) | (y > (float)HH) | (x < -1.0f) | (x > (float)WW);
        y = fmaxf(y, 0.0f);
        x = fmaxf(x, 0.0f);
        int yl = min((int)floorf(y), HH - 1);
        int xl = min((int)floorf(x), WW - 1);
        int yh = min(yl + 1, HH - 1);
        int xh = min(xl + 1, WW - 1);
        float ly = fminf(y - (float)yl, 1.0f);
        float lx = fminf(x - (float)xl, 1.0f);
        float hy = 1.0f - ly, hx = 1.0f - lx;
        float w1 = hy * hx, w2 = hy * lx, w3 = ly * hx, w4 = ly * lx;
        if (empty) { w1 = w2 = w3 = w4 = 0.0f; }

        // offsets in uint2 (=4 half) units: pixel * CC/4 = pixel * 64
        sm.o[s] = make_int4((yl * WW + xl) * (CC / 4), (yl * WW + xh) * (CC / 4),
                            (yh * WW + xl) * (CC / 4), (yh * WW + xh) * (CC / 4));
        sm.w[s] = make_float4(w1, w2, w3, w4);
    }
    if (tid == 0) sm.base_b = (int)r[0];
    __syncthreads();

    const int chunk = 2 * blockIdx.y + sub;      // 0..7
    const int b0 = 7 * chunk;
    const int live = (b0 < NBINS);               // chunk 7 idles

    if (live) {
        // thread owns channels {4lt .. 4lt+3}
        const uint2* __restrict__ f =
            g_nhwc2 + (size_t)sm.base_b * (HW * (CC / 4)) + lt;

#pragma unroll 1
        for (int bi = 0; bi < 7; bi++) {
            int bin = b0 + bi;
            int ph = bin / OUTW, pw = bin % OUTW;
            float a0 = 0.f, a1 = 0.f, a2 = 0.f, a3 = 0.f;
#pragma unroll
            for (int iy = 0; iy < SRR; iy++) {
#pragma unroll
                for (int ix = 0; ix < SRR; ix++) {
                    int s = (ph * SRR + iy) * (OUTW * SRR) + (pw * SRR + ix);
                    int4   o = sm.o[s];
                    float4 w = sm.w[s];
                    uint2 p1 = __ldg(f + o.x);
                    uint2 p2 = __ldg(f + o.y);
                    uint2 p3 = __ldg(f + o.z);
                    uint2 p4 = __ldg(f + o.w);
                    float2 va, vb;
                    va = __half22float2(*(__half2*)&p1.x);
                    vb = __half22float2(*(__half2*)&p1.y);
                    a0 += w.x * va.x; a1 += w.x * va.y;
                    a2 += w.x * vb.x; a3 += w.x * vb.y;
                    va = __half22float2(*(__half2*)&p2.x);
                    vb = __half22float2(*(__half2*)&p2.y);
                    a0 += w.y * va.x; a1 += w.y * va.y;
                    a2 += w.y * vb.x; a3 += w.y * vb.y;
                    va = __half22float2(*(__half2*)&p3.x);
                    vb = __half22float2(*(__half2*)&p3.y);
                    a0 += w.z * va.x; a1 += w.z * va.y;
                    a2 += w.z * vb.x; a3 += w.z * vb.y;
                    va = __half22float2(*(__half2*)&p4.x);
                    vb = __half22float2(*(__half2*)&p4.y);
                    a0 += w.w * va.x; a1 += w.w * va.y;
                    a2 += w.w * vb.x; a3 += w.w * vb.y;
                }
            }
            __half2 h01 = __floats2half2_rn(a0 * 0.25f, a1 * 0.25f);
            __half2 h23 = __floats2half2_rn(a2 * 0.25f, a3 * 0.25f);
            uint2 pk;
            pk.x = *(unsigned*)&h01;
            pk.y = *(unsigned*)&h23;
            *((uint2*)&sm.stage[sub][bi][0] + lt) = pk;
        }
    }
    __syncthreads();
    if (live) {
        float* __restrict__ o_roi = out + (size_t)n * (CC * NBINS);
        // coalesced flush: consecutive k -> runs of 7 consecutive floats
        for (int k = lt; k < CC * 7; k += 64) {
            int c  = k / 7;
            int bb = k - c * 7;
            o_roi[c * NBINS + b0 + bb] = __half2float(sm.stage[sub][bb][c]);
        }
    }
}

// ---------------------------------------------------------------------------
extern "C" void kernel_launch(void* const* d_in, const int* in_sizes, int n_in,
                              void* d_out, int out_size) {
    const float* feats = (const float*)d_in[0];  // (2,256,200,304) f32
    const float* rois  = (const float*)d_in[1];  // (N,6) f32
    float* out = (float*)d_out;                  // (N,256,7,7) f32
    int n_rois = in_sizes[1] / 6;

    dim3 tgrid((HW + 31) / 32, CC / 64, BB);
    nchw_to_nhwc_h<<<tgrid, dim3(32, 8)>>>(feats);

    roi_align_rotated<<<dim3(n_rois, 4), TPB>>>(rois, out);
}

// round 7
// speedup vs baseline: 1.3000x; 1.0107x over previous
#include <cuda_runtime.h>
#include <cuda_fp16.h>
#include <math.h>

#define BB 2
#define CC 256
#define HH 200
#define WW 304
#define HW (HH * WW)
#define OUTH 7
#define OUTW 7
#define NBINS (OUTH * OUTW)
#define SRR 2
#define SCALE 0.25f
#define NLOC 56            /* samples needed by one block: 2 chunks x 7 bins x 4 */

// NHWC fp16 scratch as uint2 so 8-byte gathers are guaranteed aligned.
// (B, H, W, C) halves = 62.3 MB (L2-resident).
__device__ uint2 g_nhwc2[(size_t)BB * HW * (CC / 4)];

// ---------------------------------------------------------------------------
// Kernel 1: NCHW f32 -> NHWC fp16. Tile 64 channels x 32 hw positions.
// (Near its DRAM floor: reads 249 MB f32, writes 62 MB fp16 into L2.)
// ---------------------------------------------------------------------------
__global__ __launch_bounds__(256) void nchw_to_nhwc_h(const float* __restrict__ in) {
    __shared__ float tile[64][33];
    const int b   = blockIdx.z;
    const int hw0 = blockIdx.x * 32;
    const int c0  = blockIdx.y * 64;
    const int tx  = threadIdx.x;       // 0..31
    const int ty  = threadIdx.y;       // 0..7

    const float* src = in + (size_t)b * CC * HW;
#pragma unroll
    for (int i = 0; i < 64; i += 8) {
        int c  = c0 + ty + i;
        int hw = hw0 + tx;
        float v = 0.0f;
        if (hw < HW) v = src[(size_t)c * HW + hw];
        tile[ty + i][tx] = v;
    }
    __syncthreads();

    __half2* dst = (__half2*)g_nhwc2 + (size_t)b * HW * (CC / 2);
#pragma unroll
    for (int i = 0; i < 32; i += 8) {
        int hw = hw0 + ty + i;
        if (hw < HW) {
            float va = tile[2 * tx][ty + i];
            float vb = tile[2 * tx + 1][ty + i];
            dst[((size_t)hw * CC + c0) / 2 + tx] = __floats2half2_rn(va, vb);
        }
    }
}

// ---------------------------------------------------------------------------
// Kernel 2: rotated ROI align on fp16 NHWC.
// Grid (n_rois, 4), block 128 = 2 subgroups of 64 threads; subgroup handles
// ONE 7-bin chunk (chunk = 2*y+sub, chunk 7 idles). Setup computes ONLY the
// 56 samples this block needs (one tid<56 pass, __sincosf fast path).
// 4 ch/thread via uint2 (8B) gathers, fp32 accumulation, fp16 stage,
// coalesced f32 flush. smem ~9.3KB, 12 blocks/SM target.
// ---------------------------------------------------------------------------
#define TPB 128

struct AlignSmem {
    int4   o[NLOC];              // 4 corner offsets in uint2 units (pix*64)
    float4 w[NLOC];              // 4 bilinear weights (zeroed if empty)
    __half stage[2][7][264];     // [subgroup][bin-in-chunk][channel(+pad)]
    int    base_b;
};

__global__ __launch_bounds__(TPB, 12) void roi_align_rotated(
    const float* __restrict__ rois, float* __restrict__ out) {
    __shared__ AlignSmem sm;
    const int n   = blockIdx.x;
    const int tid = threadIdx.x;
    const int sub = tid >> 6;        // 0/1: chunk subgroup
    const int lt  = tid & 63;        // channel-group lane
    const float* r = rois + (size_t)n * 6;

    if (tid < NLOC) {
        // local sample t -> (sub, bin-in-chunk, iy, ix)
        const int tsub = tid / 28;
        const int rest = tid - tsub * 28;
        const int bi   = rest >> 2;
        const int iy   = (rest >> 1) & 1;
        const int ix   = rest & 1;
        const int bin  = 7 * (2 * blockIdx.y + tsub) + bi;   // may be >=49 (unused)
        const int ph   = bin / OUTW;
        const int pw   = bin - ph * OUTW;
        const int i = ph * SRR + iy;      // y sample index
        const int j = pw * SRR + ix;      // x sample index

        float cw = r[1] * SCALE - 0.5f;
        float ch = r[2] * SCALE - 0.5f;
        float rw = r[3] * SCALE;
        float rh = r[4] * SCALE;
        float theta = r[5] * (float)(M_PI / 180.0);
        float st, ct;
        __sincosf(theta, &st, &ct);

        float bin_h = rh * (1.0f / OUTH);
        float bin_w = rw * (1.0f / OUTW);
        float ty = (i + 0.5f) * (1.0f / SRR);
        float tx = (j + 0.5f) * (1.0f / SRR);
        float yy = -rh * 0.5f + ty * bin_h;
        float xx = -rw * 0.5f + tx * bin_w;
        float y = yy * ct - xx * st + ch;
        float x = yy * st + xx * ct + cw;

        bool empty = (y < -1.0f) | (y > (float)HH) | (x < -1.0f) | (x > (float)WW);
        y = fmaxf(y, 0.0f);
        x = fmaxf(x, 0.0f);
        int yl = min((int)floorf(y), HH - 1);
        int xl = min((int)floorf(x), WW - 1);
        int yh = min(yl + 1, HH - 1);
        int xh = min(xl + 1, WW - 1);
        float ly = fminf(y - (float)yl, 1.0f);
        float lx = fminf(x - (float)xl, 1.0f);
        float hy = 1.0f - ly, hx = 1.0f - lx;
        float w1 = hy * hx, w2 = hy * lx, w3 = ly * hx, w4 = ly * lx;
        if (empty) { w1 = w2 = w3 = w4 = 0.0f; }

        // offsets in uint2 (=4 half) units: pixel * CC/4 = pixel * 64
        sm.o[tid] = make_int4((yl * WW + xl) * (CC / 4), (yl * WW + xh) * (CC / 4),
                              (yh * WW + xl) * (CC / 4), (yh * WW + xh) * (CC / 4));
        sm.w[tid] = make_float4(w1, w2, w3, w4);
    }
    if (tid == 0) sm.base_b = (int)r[0];
    __syncthreads();

    const int chunk = 2 * blockIdx.y + sub;      // 0..7
    const int b0 = 7 * chunk;
    const int live = (b0 < NBINS);               // chunk 7 idles

    if (live) {
        // thread owns channels {4lt .. 4lt+3}
        const uint2* __restrict__ f =
            g_nhwc2 + (size_t)sm.base_b * (HW * (CC / 4)) + lt;

#pragma unroll 1
        for (int bi = 0; bi < 7; bi++) {
            const int t0 = sub * 28 + bi * 4;
            float a0 = 0.f, a1 = 0.f, a2 = 0.f, a3 = 0.f;
#pragma unroll
            for (int q = 0; q < 4; q++) {
                int4   o = sm.o[t0 + q];
                float4 w = sm.w[t0 + q];
                uint2 p1 = __ldg(f + o.x);
                uint2 p2 = __ldg(f + o.y);
                uint2 p3 = __ldg(f + o.z);
                uint2 p4 = __ldg(f + o.w);
                float2 va, vb;
                va = __half22float2(*(__half2*)&p1.x);
                vb = __half22float2(*(__half2*)&p1.y);
                a0 += w.x * va.x; a1 += w.x * va.y;
                a2 += w.x * vb.x; a3 += w.x * vb.y;
                va = __half22float2(*(__half2*)&p2.x);
                vb = __half22float2(*(__half2*)&p2.y);
                a0 += w.y * va.x; a1 += w.y * va.y;
                a2 += w.y * vb.x; a3 += w.y * vb.y;
                va = __half22float2(*(__half2*)&p3.x);
                vb = __half22float2(*(__half2*)&p3.y);
                a0 += w.z * va.x; a1 += w.z * va.y;
                a2 += w.z * vb.x; a3 += w.z * vb.y;
                va = __half22float2(*(__half2*)&p4.x);
                vb = __half22float2(*(__half2*)&p4.y);
                a0 += w.w * va.x; a1 += w.w * va.y;
                a2 += w.w * vb.x; a3 += w.w * vb.y;
            }
            __half2 h01 = __floats2half2_rn(a0 * 0.25f, a1 * 0.25f);
            __half2 h23 = __floats2half2_rn(a2 * 0.25f, a3 * 0.25f);
            uint2 pk;
            pk.x = *(unsigned*)&h01;
            pk.y = *(unsigned*)&h23;
            *((uint2*)&sm.stage[sub][bi][0] + lt) = pk;
        }
    }
    __syncthreads();
    if (live) {
        float* __restrict__ o_roi = out + (size_t)n * (CC * NBINS);
        // coalesced flush: consecutive k -> runs of 7 consecutive floats
        for (int k = lt; k < CC * 7; k += 64) {
            int c  = k / 7;
            int bb = k - c * 7;
            o_roi[c * NBINS + b0 + bb] = __half2float(sm.stage[sub][bb][c]);
        }
    }
}

// ---------------------------------------------------------------------------
extern "C" void kernel_launch(void* const* d_in, const int* in_sizes, int n_in,
                              void* d_out, int out_size) {
    const float* feats = (const float*)d_in[0];  // (2,256,200,304) f32
    const float* rois  = (const float*)d_in[1];  // (N,6) f32
    float* out = (float*)d_out;                  // (N,256,7,7) f32
    int n_rois = in_sizes[1] / 6;

    dim3 tgrid((HW + 31) / 32, CC / 64, BB);
    nchw_to_nhwc_h<<<tgrid, dim3(32, 8)>>>(feats);

    roi_align_rotated<<<dim3(n_rois, 4), TPB>>>(rois, out);
}